// round 7
// baseline (speedup 1.0000x reference)
#include <cuda_runtime.h>
#include <cstdint>
#include <cstddef>

#define NB 8
#define NN 2048
#define MM 256
#define GG 1024  // 4*MM

// ---------------- device-global scratch (no allocations allowed) -----------
__device__ float g_Q[NB * NN * MM];   // q_t per (batch, step)   16 MB
__device__ float g_K[NB * NN * MM];   // keys                    16 MB
__device__ float g_xb[GG];            // x_proj + b_ih + b_hh

// ---------------- helpers --------------------------------------------------
__device__ __forceinline__ uint32_t smem_u32(const void* p) {
    return (uint32_t)__cvta_generic_to_shared(p);
}
__device__ __forceinline__ uint32_t mapa_rank(uint32_t laddr, uint32_t rank) {
    uint32_t r;
    asm("mapa.shared::cluster.u32 %0, %1, %2;" : "=r"(r) : "r"(laddr), "r"(rank));
    return r;
}
__device__ __forceinline__ void st_cluster_f32(uint32_t addr, float v) {
    asm volatile("st.shared::cluster.f32 [%0], %1;" :: "r"(addr), "f"(v) : "memory");
}
__device__ __forceinline__ void cluster_sync_() {
    asm volatile("barrier.cluster.arrive.aligned;" ::: "memory");
    asm volatile("barrier.cluster.wait.aligned;" ::: "memory");
}
__device__ __forceinline__ uint32_t fkey(float f) {
    uint32_t u = __float_as_uint(f);
    return (u & 0x80000000u) ? ~u : (u | 0x80000000u);  // monotonic float->uint
}
__device__ __forceinline__ float sigm(float x) { return 1.0f / (1.0f + expf(-x)); }

// ---------------- setup: g_xb = w_ih @ dec + b_ih + b_hh -------------------
__global__ void __launch_bounds__(1024) k_setup(
    const float* __restrict__ w_ih, const float* __restrict__ b_ih,
    const float* __restrict__ b_hh, const float* __restrict__ dec) {
    __shared__ __align__(16) float ds[MM];
    int g = threadIdx.x;
    if (g < MM) ds[g] = dec[g];
    __syncthreads();
    const float4* w4 = (const float4*)(w_ih + (size_t)g * MM);
    const float4* d4 = (const float4*)ds;
    float acc = 0.f;
#pragma unroll 16
    for (int i = 0; i < MM / 4; i++) {
        float4 w = w4[i], d = d4[i];
        acc += w.x * d.x + w.y * d.y + w.z * d.z + w.w * d.w;
    }
    g_xb[g] = acc + b_ih[g] + b_hh[g];
}

// ---------------- phase 1: LSTM scan, 8-CTA cluster per batch --------------
// CTA rank r owns gates [r*128, r*128+128) (2 threads/gate, 128 K-elems each,
// weights in registers) and q outputs [r*32, r*32+32) (8 threads/output).
// Gates broadcast to all 8 CTAs via DSMEM stores; one cluster sync per step.
__global__ void __cluster_dims__(8, 1, 1) __launch_bounds__(256, 1)
k_lstm(const float* __restrict__ w_hh, const float* __restrict__ Wq,
       const float* __restrict__ bq, const float* __restrict__ z_g,
       const float* __restrict__ h0) {
    int tid = threadIdx.x;
    uint32_t rk;
    asm("mov.u32 %0, %%cluster_ctarank;" : "=r"(rk));
    int b = blockIdx.x >> 3;

    __shared__ __align__(16) float h_sm[MM];
    __shared__ __align__(16) float c_sm[MM];
    __shared__ __align__(16) float gbuf[2][GG];

    // gate shard
    int gl = tid >> 1;
    int g = (int)rk * 128 + gl;
    int kh = tid & 1;
    float wr[128];
    {
        const float4* w4 = (const float4*)(w_hh + (size_t)g * MM + kh * 128);
#pragma unroll
        for (int i = 0; i < 32; i++) {
            float4 v = w4[i];
            wr[4 * i] = v.x; wr[4 * i + 1] = v.y; wr[4 * i + 2] = v.z; wr[4 * i + 3] = v.w;
        }
    }
    float xb = g_xb[g];

    // q shard
    int jl = tid >> 3, ks = tid & 7;
    int jq = (int)rk * 32 + jl;
    float wq[32];
    {
        const float4* q4 = (const float4*)(Wq + (size_t)jq * MM + ks * 32);
#pragma unroll
        for (int i = 0; i < 8; i++) {
            float4 v = q4[i];
            wq[4 * i] = v.x; wq[4 * i + 1] = v.y; wq[4 * i + 2] = v.z; wq[4 * i + 3] = v.w;
        }
    }
    float bqv = bq[jq];

    // remote gate-slot addresses (one per cluster rank)
    uint32_t ra[8];
    {
        uint32_t la = smem_u32(&gbuf[0][g]);
#pragma unroll
        for (int r = 0; r < 8; r++) ra[r] = mapa_rank(la, (uint32_t)r);
    }

    h_sm[tid] = h0[tid];
    c_sm[tid] = z_g[b * MM + tid];
    __syncthreads();

    float* Qb = g_Q + (size_t)b * NN * MM;

    for (int t = 0; t < NN; t++) {
        // gates GEMV from register weights + smem h (broadcast LDS)
        const float4* h4 = (const float4*)(h_sm + kh * 128);
        float acc = 0.f;
#pragma unroll
        for (int i = 0; i < 32; i++) {
            float4 hv = h4[i];
            acc += wr[4 * i] * hv.x + wr[4 * i + 1] * hv.y
                 + wr[4 * i + 2] * hv.z + wr[4 * i + 3] * hv.w;
        }
        acc += __shfl_xor_sync(0xffffffffu, acc, 1);
        if (kh == 0) {
            float val = acc + xb;
            uint32_t off = (uint32_t)((t & 1) * (GG * 4));
#pragma unroll
            for (int r = 0; r < 8; r++) st_cluster_f32(ra[r] + off, val);
        }
        cluster_sync_();  // gates of step t visible in every CTA

        // pointwise (replicated per CTA; thread == element)
        {
            const float* gb = gbuf[t & 1];
            float gi = gb[tid], gf = gb[256 + tid], gg = gb[512 + tid], go = gb[768 + tid];
            float c = sigm(gf) * c_sm[tid] + sigm(gi) * tanhf(gg);
            c_sm[tid] = c;
            h_sm[tid] = sigm(go) * tanhf(c);
        }
        __syncthreads();  // h complete before q GEMV / next gate GEMV

        // q_t shard
        {
            const float4* hq = (const float4*)(h_sm + ks * 32);
            float qa = 0.f;
#pragma unroll
            for (int i = 0; i < 8; i++) {
                float4 hv = hq[i];
                qa += wq[4 * i] * hv.x + wq[4 * i + 1] * hv.y
                    + wq[4 * i + 2] * hv.z + wq[4 * i + 3] * hv.w;
            }
            qa += __shfl_xor_sync(0xffffffffu, qa, 4);
            qa += __shfl_xor_sync(0xffffffffu, qa, 2);
            qa += __shfl_xor_sync(0xffffffffu, qa, 1);
            if (ks == 0) Qb[(size_t)t * MM + jq] = qa + bqv;
        }
    }
}

// ---------------- phase 2: C = A @ B^T (+bias), K=256 hardcoded ------------
// A: [*,256] row-major, B: [*,256] row-major, C: [*,ldc]. 128x128 tiles,
// BK=16, 256 threads, 8x8 micro-tiles. All dims multiples of 128.
__global__ void __launch_bounds__(256) k_gemm_nt(
    const float* __restrict__ A, const float* __restrict__ B,
    const float* __restrict__ bias, float* __restrict__ C,
    size_t sA, size_t sB, size_t sC, int ldc) {
    A += (size_t)blockIdx.z * sA;
    B += (size_t)blockIdx.z * sB;
    C += (size_t)blockIdx.z * sC;
    int row0 = blockIdx.y * 128, col0 = blockIdx.x * 128;

    __shared__ __align__(16) float As[16][132];
    __shared__ __align__(16) float Bs[16][132];

    int tid = threadIdx.x;
    int tx = tid & 15, ty = tid >> 4;
    float acc[8][8] = {};

    for (int kt = 0; kt < 256; kt += 16) {
#pragma unroll
        for (int l = 0; l < 2; l++) {
            int f = tid + 256 * l;
            int i = f >> 2, c4 = (f & 3) * 4;
            float4 a = *(const float4*)(A + (size_t)(row0 + i) * 256 + kt + c4);
            As[c4 + 0][i] = a.x; As[c4 + 1][i] = a.y; As[c4 + 2][i] = a.z; As[c4 + 3][i] = a.w;
            float4 bv = *(const float4*)(B + (size_t)(col0 + i) * 256 + kt + c4);
            Bs[c4 + 0][i] = bv.x; Bs[c4 + 1][i] = bv.y; Bs[c4 + 2][i] = bv.z; Bs[c4 + 3][i] = bv.w;
        }
        __syncthreads();
#pragma unroll
        for (int kk = 0; kk < 16; kk++) {
            float a[8], bb[8];
            float4 t0 = *(const float4*)(&As[kk][ty * 8]);
            float4 t1 = *(const float4*)(&As[kk][ty * 8 + 4]);
            a[0] = t0.x; a[1] = t0.y; a[2] = t0.z; a[3] = t0.w;
            a[4] = t1.x; a[5] = t1.y; a[6] = t1.z; a[7] = t1.w;
            float4 u0 = *(const float4*)(&Bs[kk][tx * 8]);
            float4 u1 = *(const float4*)(&Bs[kk][tx * 8 + 4]);
            bb[0] = u0.x; bb[1] = u0.y; bb[2] = u0.z; bb[3] = u0.w;
            bb[4] = u1.x; bb[5] = u1.y; bb[6] = u1.z; bb[7] = u1.w;
#pragma unroll
            for (int i = 0; i < 8; i++)
#pragma unroll
                for (int j = 0; j < 8; j++) acc[i][j] += a[i] * bb[j];
        }
        __syncthreads();
    }

    float bs[8];
#pragma unroll
    for (int j = 0; j < 8; j++) bs[j] = bias ? bias[col0 + tx * 8 + j] : 0.f;

#pragma unroll
    for (int i = 0; i < 8; i++) {
        float* cp = C + (size_t)(row0 + ty * 8 + i) * ldc + col0 + tx * 8;
        float4 v0 = make_float4(acc[i][0] + bs[0], acc[i][1] + bs[1],
                                acc[i][2] + bs[2], acc[i][3] + bs[3]);
        float4 v1 = make_float4(acc[i][4] + bs[4], acc[i][5] + bs[5],
                                acc[i][6] + bs[6], acc[i][7] + bs[7]);
        *(float4*)cp = v0;
        *(float4*)(cp + 4) = v1;
    }
}

// ---------------- phase 3: sequential masked softmax/argmax chain ----------
// One CTA (1024 threads) per batch; 2 elems/thread; used-flags in registers;
// fused (packed-argmax, sum-exp) reduction; one __syncthreads per step.
__global__ void __launch_bounds__(1024, 1) k_chain(float* __restrict__ out) {
    int b = blockIdx.x;
    int tid = threadIdx.x;
    int lane = tid & 31, warp = tid >> 5;
    float* base = out + (size_t)b * NN * NN;
    int n0 = tid * 2;
    bool u0 = false, u1 = false;

    __shared__ unsigned long long pk_s[2][32];
    __shared__ float sm_s[2][32];

    float2 cur = *(const float2*)(base + n0);  // row 0 prefetched
    for (int t = 0; t < NN; t++) {
        float2 nxt = cur;
        if (t + 1 < NN) nxt = *(const float2*)(base + (size_t)(t + 1) * NN + n0);

        float s0 = cur.x, s1 = cur.y;
        unsigned long long p0 = u0 ? 0ull
            : (((unsigned long long)fkey(s0)) << 32) | (uint32_t)(~(uint32_t)n0);
        unsigned long long p1 = u1 ? 0ull
            : (((unsigned long long)fkey(s1)) << 32) | (uint32_t)(~(uint32_t)(n0 + 1));
        float e0 = u0 ? 0.f : expf(s0);
        float e1 = u1 ? 0.f : expf(s1);
        unsigned long long pk = p0 > p1 ? p0 : p1;
        float sm = e0 + e1;
#pragma unroll
        for (int m = 16; m; m >>= 1) {
            unsigned long long o = __shfl_xor_sync(0xffffffffu, pk, m);
            pk = o > pk ? o : pk;
            sm += __shfl_xor_sync(0xffffffffu, sm, m);
        }
        if (lane == 0) { pk_s[t & 1][warp] = pk; sm_s[t & 1][warp] = sm; }
        __syncthreads();
        pk = pk_s[t & 1][lane];
        sm = sm_s[t & 1][lane];
#pragma unroll
        for (int m = 16; m; m >>= 1) {
            unsigned long long o = __shfl_xor_sync(0xffffffffu, pk, m);
            pk = o > pk ? o : pk;
            sm += __shfl_xor_sync(0xffffffffu, sm, m);
        }
        float inv = __fdividef(1.f, sm);
        *(float2*)(base + (size_t)t * NN + n0) = make_float2(e0 * inv, e1 * inv);
        uint32_t win = ~(uint32_t)(pk & 0xffffffffull);
        u0 |= (win == (uint32_t)n0);
        u1 |= (win == (uint32_t)(n0 + 1));
        cur = nxt;
    }
}

// ---------------- launch ---------------------------------------------------
extern "C" void kernel_launch(void* const* d_in, const int* in_sizes, int n_in,
                              void* d_out, int out_size) {
    const float* node = (const float*)d_in[0];
    const float* z_g  = (const float*)d_in[1];
    const float* dec  = (const float*)d_in[2];
    const float* h0   = (const float*)d_in[3];
    const float* w_ih = (const float*)d_in[4];
    const float* w_hh = (const float*)d_in[5];
    const float* b_ih = (const float*)d_in[6];
    const float* b_hh = (const float*)d_in[7];
    const float* Wq   = (const float*)d_in[8];
    const float* bq   = (const float*)d_in[9];
    const float* Wk   = (const float*)d_in[10];
    const float* bk   = (const float*)d_in[11];
    float* out = (float*)d_out;

    float* dQ = nullptr;
    float* dK = nullptr;
    cudaGetSymbolAddress((void**)&dQ, g_Q);
    cudaGetSymbolAddress((void**)&dK, g_K);

    // setup (x_proj + biases)
    k_setup<<<1, 1024>>>(w_ih, b_ih, b_hh, dec);

    // keys = node_emb @ Wk^T + bk   (M = 8*2048 flat, N = 256)
    k_gemm_nt<<<dim3(2, 128, 1), 256>>>(node, Wk, bk, dK, 0, 0, 0, 256);

    // LSTM scan -> g_Q
    k_lstm<<<64, 256>>>(w_hh, Wq, bq, z_g, h0);

    // S = Q @ K^T written straight into d_out (per batch)
    k_gemm_nt<<<dim3(16, 16, 8), 256>>>(dQ, dK, nullptr, out,
                                        (size_t)NN * MM, (size_t)NN * MM,
                                        (size_t)NN * NN, NN);

    // in-place masked softmax / argmax chain
    k_chain<<<8, 1024>>>(out);
}

// round 8
// speedup vs baseline: 1.0457x; 1.0457x over previous
#include <cuda_runtime.h>
#include <cstdint>
#include <cstddef>

#define NB 8
#define NN 2048
#define MM 256
#define GG 1024  // 4*MM

// ---------------- device-global scratch (no allocations allowed) -----------
__device__ float g_Q[NB * NN * MM];   // q_t per (batch, step)   16 MB
__device__ float g_K[NB * NN * MM];   // keys                    16 MB
__device__ float g_xb[GG];            // x_proj + b_ih + b_hh

// ---------------- helpers --------------------------------------------------
__device__ __forceinline__ uint32_t smem_u32(const void* p) {
    return (uint32_t)__cvta_generic_to_shared(p);
}
__device__ __forceinline__ uint32_t mapa_rank(uint32_t laddr, uint32_t rank) {
    uint32_t r;
    asm("mapa.shared::cluster.u32 %0, %1, %2;" : "=r"(r) : "r"(laddr), "r"(rank));
    return r;
}
__device__ __forceinline__ void st_cluster_f32(uint32_t addr, float v) {
    asm volatile("st.shared::cluster.f32 [%0], %1;" :: "r"(addr), "f"(v) : "memory");
}
__device__ __forceinline__ void cluster_sync_() {
    asm volatile("barrier.cluster.arrive.aligned;" ::: "memory");
    asm volatile("barrier.cluster.wait.aligned;" ::: "memory");
}
__device__ __forceinline__ uint32_t fkey(float f) {
    uint32_t u = __float_as_uint(f);
    return (u & 0x80000000u) ? ~u : (u | 0x80000000u);  // monotonic float->uint
}
__device__ __forceinline__ float sigm(float x) { return 1.0f / (1.0f + expf(-x)); }

// packed f32x2 ops (sm_103a; ptxas never auto-fuses these)
__device__ __forceinline__ uint64_t fma2(uint64_t a, uint64_t b, uint64_t c) {
    uint64_t d;
    asm("fma.rn.f32x2 %0, %1, %2, %3;" : "=l"(d) : "l"(a), "l"(b), "l"(c));
    return d;
}
__device__ __forceinline__ uint64_t add2(uint64_t a, uint64_t b) {
    uint64_t d;
    asm("add.rn.f32x2 %0, %1, %2;" : "=l"(d) : "l"(a), "l"(b));
    return d;
}
__device__ __forceinline__ uint64_t pack2(float lo, float hi) {
    uint64_t d;
    asm("mov.b64 %0, {%1, %2};" : "=l"(d) : "r"(__float_as_uint(lo)), "r"(__float_as_uint(hi)));
    return d;
}
__device__ __forceinline__ float unpack_sum(uint64_t a) {
    uint32_t lo, hi;
    asm("mov.b64 {%0, %1}, %2;" : "=r"(lo), "=r"(hi) : "l"(a));
    return __uint_as_float(lo) + __uint_as_float(hi);
}
__device__ __forceinline__ void unpack2(uint64_t a, float& lo, float& hi) {
    uint32_t l, h;
    asm("mov.b64 {%0, %1}, %2;" : "=r"(l), "=r"(h) : "l"(a));
    lo = __uint_as_float(l); hi = __uint_as_float(h);
}

// ---------------- setup: g_xb = w_ih @ dec + b_ih + b_hh -------------------
__global__ void __launch_bounds__(1024) k_setup(
    const float* __restrict__ w_ih, const float* __restrict__ b_ih,
    const float* __restrict__ b_hh, const float* __restrict__ dec) {
    __shared__ __align__(16) float ds[MM];
    int g = threadIdx.x;
    if (g < MM) ds[g] = dec[g];
    __syncthreads();
    const float4* w4 = (const float4*)(w_ih + (size_t)g * MM);
    const float4* d4 = (const float4*)ds;
    float acc = 0.f;
#pragma unroll 16
    for (int i = 0; i < MM / 4; i++) {
        float4 w = w4[i], d = d4[i];
        acc += w.x * d.x + w.y * d.y + w.z * d.z + w.w * d.w;
    }
    g_xb[g] = acc + b_ih[g] + b_hh[g];
}

// ---------------- phase 1: LSTM scan, 8-CTA cluster per batch --------------
// CTA rank r owns h elements [r*32, r*32+32): it computes the 128 gate rows
// feeding those elements (2 threads/row, 128 K-elems each, weights in regs as
// packed f32x2), does the pointwise locally (c in registers), and broadcasts
// its 32 new h values to all 8 CTAs' double-buffered h_sm via DSMEM.
// Exactly one __syncthreads + one cluster barrier per step.
__global__ void __cluster_dims__(8, 1, 1) __launch_bounds__(256, 1)
k_lstm(const float* __restrict__ w_hh, const float* __restrict__ Wq,
       const float* __restrict__ bq, const float* __restrict__ z_g,
       const float* __restrict__ h0) {
    int tid = threadIdx.x;
    uint32_t rk;
    asm("mov.u32 %0, %%cluster_ctarank;" : "=r"(rk));
    int b = blockIdx.x >> 3;

    __shared__ __align__(16) float h_sm[2][MM];   // cluster-written, dbl-buffered
    __shared__ __align__(16) float gloc[128];     // local gates [g4*32 + j]

    // gate shard: row rloc = tid>>1 in [0,128); g4 = gate type; j = local elem
    int rloc = tid >> 1;
    int kh = tid & 1;
    int g4 = rloc >> 5, j = rloc & 31;
    int grow = g4 * 256 + (int)rk * 32 + j;       // global w_hh row
    uint64_t wg[64];                               // 128 weights packed
    {
        const uint64_t* wp = (const uint64_t*)(w_hh + (size_t)grow * MM + kh * 128);
#pragma unroll
        for (int i = 0; i < 64; i++) wg[i] = wp[i];
    }
    float xb = g_xb[grow];

    // q shard: 32 rows, 8 threads/row, 32 K-elems each
    int qrow = (int)rk * 32 + (tid >> 3);
    int ks = tid & 7;
    uint64_t wq2[16];
    {
        const uint64_t* qp = (const uint64_t*)(Wq + (size_t)qrow * MM + ks * 32);
#pragma unroll
        for (int i = 0; i < 16; i++) wq2[i] = qp[i];
    }
    float bqv = bq[qrow];

    // remote h_sm base addresses (one per rank)
    uint32_t ha[8];
    {
        uint32_t la = smem_u32(&h_sm[0][0]);
#pragma unroll
        for (int r = 0; r < 8; r++) ha[r] = mapa_rank(la, (uint32_t)r);
    }

    // init: h(-1) into buffer 0 (every CTA holds a full copy); c in registers
    h_sm[0][tid] = h0[tid];
    float c_reg = 0.f;
    if (tid < 32) c_reg = z_g[b * MM + (int)rk * 32 + tid];
    __syncthreads();
    cluster_sync_();

    float* Qb = g_Q + (size_t)b * NN * MM;

    for (int t = 0; t < NN; t++) {
        // ---- gate GEMV: 64 packed FMAs from register weights + smem h -----
        {
            const uint64_t* h2 = (const uint64_t*)(h_sm[t & 1] + kh * 128);
            uint64_t a0 = 0, a1 = 0, a2 = 0, a3 = 0;
#pragma unroll
            for (int i = 0; i < 64; i += 4) {
                a0 = fma2(wg[i + 0], h2[i + 0], a0);
                a1 = fma2(wg[i + 1], h2[i + 1], a1);
                a2 = fma2(wg[i + 2], h2[i + 2], a2);
                a3 = fma2(wg[i + 3], h2[i + 3], a3);
            }
            float s = unpack_sum(add2(add2(a0, a1), add2(a2, a3)));
            s += __shfl_xor_sync(0xffffffffu, s, 1);
            if (kh == 0) gloc[rloc] = s + xb;
        }
        __syncthreads();

        // ---- pointwise for the 32 owned elements; broadcast new h ---------
        if (tid < 32) {
            float gi = gloc[tid], gf = gloc[32 + tid];
            float gg = gloc[64 + tid], go = gloc[96 + tid];
            float c = sigm(gf) * c_reg + sigm(gi) * tanhf(gg);
            c_reg = c;
            float hv = sigm(go) * tanhf(c);
            uint32_t off = (uint32_t)((((t + 1) & 1) * MM + (int)rk * 32 + tid) * 4);
#pragma unroll
            for (int r = 0; r < 8; r++) st_cluster_f32(ha[r] + off, hv);
        }
        cluster_sync_();  // h(t) visible everywhere

        // ---- q_t shard -----------------------------------------------------
        {
            const uint64_t* hq = (const uint64_t*)(h_sm[(t + 1) & 1] + ks * 32);
            uint64_t b0 = 0, b1 = 0;
#pragma unroll
            for (int i = 0; i < 16; i += 2) {
                b0 = fma2(wq2[i], hq[i], b0);
                b1 = fma2(wq2[i + 1], hq[i + 1], b1);
            }
            float q = unpack_sum(add2(b0, b1));
            q += __shfl_xor_sync(0xffffffffu, q, 4);
            q += __shfl_xor_sync(0xffffffffu, q, 2);
            q += __shfl_xor_sync(0xffffffffu, q, 1);
            if (ks == 0) Qb[(size_t)t * MM + qrow] = q + bqv;
        }
    }
}

// ---------------- phase 2: C = A @ B^T (+bias), K=256, packed f32x2 --------
__global__ void __launch_bounds__(256) k_gemm_nt(
    const float* __restrict__ A, const float* __restrict__ B,
    const float* __restrict__ bias, float* __restrict__ C,
    size_t sA, size_t sB, size_t sC, int ldc) {
    A += (size_t)blockIdx.z * sA;
    B += (size_t)blockIdx.z * sB;
    C += (size_t)blockIdx.z * sC;
    int row0 = blockIdx.y * 128, col0 = blockIdx.x * 128;

    __shared__ __align__(16) float As[16][132];
    __shared__ __align__(16) float Bs[16][132];

    int tid = threadIdx.x;
    int tx = tid & 15, ty = tid >> 4;
    uint64_t acc2[8][4] = {};

    for (int kt = 0; kt < 256; kt += 16) {
#pragma unroll
        for (int l = 0; l < 2; l++) {
            int f = tid + 256 * l;
            int i = f >> 2, c4 = (f & 3) * 4;
            float4 a = *(const float4*)(A + (size_t)(row0 + i) * 256 + kt + c4);
            As[c4 + 0][i] = a.x; As[c4 + 1][i] = a.y; As[c4 + 2][i] = a.z; As[c4 + 3][i] = a.w;
            float4 bv = *(const float4*)(B + (size_t)(col0 + i) * 256 + kt + c4);
            Bs[c4 + 0][i] = bv.x; Bs[c4 + 1][i] = bv.y; Bs[c4 + 2][i] = bv.z; Bs[c4 + 3][i] = bv.w;
        }
        __syncthreads();
#pragma unroll
        for (int kk = 0; kk < 16; kk++) {
            float4 t0 = *(const float4*)(&As[kk][ty * 8]);
            float4 t1 = *(const float4*)(&As[kk][ty * 8 + 4]);
            uint64_t ad[8];
            ad[0] = pack2(t0.x, t0.x); ad[1] = pack2(t0.y, t0.y);
            ad[2] = pack2(t0.z, t0.z); ad[3] = pack2(t0.w, t0.w);
            ad[4] = pack2(t1.x, t1.x); ad[5] = pack2(t1.y, t1.y);
            ad[6] = pack2(t1.z, t1.z); ad[7] = pack2(t1.w, t1.w);
            const uint64_t* bsp = (const uint64_t*)(&Bs[kk][tx * 8]);
            uint64_t bp0 = bsp[0], bp1 = bsp[1], bp2 = bsp[2], bp3 = bsp[3];
#pragma unroll
            for (int i = 0; i < 8; i++) {
                acc2[i][0] = fma2(ad[i], bp0, acc2[i][0]);
                acc2[i][1] = fma2(ad[i], bp1, acc2[i][1]);
                acc2[i][2] = fma2(ad[i], bp2, acc2[i][2]);
                acc2[i][3] = fma2(ad[i], bp3, acc2[i][3]);
            }
        }
        __syncthreads();
    }

    float bs[8];
#pragma unroll
    for (int jj = 0; jj < 8; jj++) bs[jj] = bias ? bias[col0 + tx * 8 + jj] : 0.f;

#pragma unroll
    for (int i = 0; i < 8; i++) {
        float v[8];
#pragma unroll
        for (int jp = 0; jp < 4; jp++) unpack2(acc2[i][jp], v[2 * jp], v[2 * jp + 1]);
        float* cp = C + (size_t)(row0 + ty * 8 + i) * ldc + col0 + tx * 8;
        float4 v0 = make_float4(v[0] + bs[0], v[1] + bs[1], v[2] + bs[2], v[3] + bs[3]);
        float4 v1 = make_float4(v[4] + bs[4], v[5] + bs[5], v[6] + bs[6], v[7] + bs[7]);
        *(float4*)cp = v0;
        *(float4*)(cp + 4) = v1;
    }
}

// ---------------- phase 3: sequential masked softmax/argmax chain ----------
__global__ void __launch_bounds__(1024, 1) k_chain(float* __restrict__ out) {
    int b = blockIdx.x;
    int tid = threadIdx.x;
    int lane = tid & 31, warp = tid >> 5;
    float* base = out + (size_t)b * NN * NN;
    int n0 = tid * 2;
    bool u0 = false, u1 = false;

    __shared__ unsigned long long pk_s[2][32];
    __shared__ float sm_s[2][32];

    float2 cur = *(const float2*)(base + n0);  // row 0 prefetched
    for (int t = 0; t < NN; t++) {
        float2 nxt = cur;
        if (t + 1 < NN) nxt = *(const float2*)(base + (size_t)(t + 1) * NN + n0);

        float s0 = cur.x, s1 = cur.y;
        unsigned long long p0 = u0 ? 0ull
            : (((unsigned long long)fkey(s0)) << 32) | (uint32_t)(~(uint32_t)n0);
        unsigned long long p1 = u1 ? 0ull
            : (((unsigned long long)fkey(s1)) << 32) | (uint32_t)(~(uint32_t)(n0 + 1));
        float e0 = u0 ? 0.f : expf(s0);
        float e1 = u1 ? 0.f : expf(s1);
        unsigned long long pk = p0 > p1 ? p0 : p1;
        float sm = e0 + e1;
#pragma unroll
        for (int m = 16; m; m >>= 1) {
            unsigned long long o = __shfl_xor_sync(0xffffffffu, pk, m);
            pk = o > pk ? o : pk;
            sm += __shfl_xor_sync(0xffffffffu, sm, m);
        }
        if (lane == 0) { pk_s[t & 1][warp] = pk; sm_s[t & 1][warp] = sm; }
        __syncthreads();
        pk = pk_s[t & 1][lane];
        sm = sm_s[t & 1][lane];
#pragma unroll
        for (int m = 16; m; m >>= 1) {
            unsigned long long o = __shfl_xor_sync(0xffffffffu, pk, m);
            pk = o > pk ? o : pk;
            sm += __shfl_xor_sync(0xffffffffu, sm, m);
        }
        float inv = __fdividef(1.f, sm);
        *(float2*)(base + (size_t)t * NN + n0) = make_float2(e0 * inv, e1 * inv);
        uint32_t win = ~(uint32_t)(pk & 0xffffffffull);
        u0 |= (win == (uint32_t)n0);
        u1 |= (win == (uint32_t)(n0 + 1));
        cur = nxt;
    }
}

// ---------------- launch ---------------------------------------------------
extern "C" void kernel_launch(void* const* d_in, const int* in_sizes, int n_in,
                              void* d_out, int out_size) {
    const float* node = (const float*)d_in[0];
    const float* z_g  = (const float*)d_in[1];
    const float* dec  = (const float*)d_in[2];
    const float* h0   = (const float*)d_in[3];
    const float* w_ih = (const float*)d_in[4];
    const float* w_hh = (const float*)d_in[5];
    const float* b_ih = (const float*)d_in[6];
    const float* b_hh = (const float*)d_in[7];
    const float* Wq   = (const float*)d_in[8];
    const float* bq   = (const float*)d_in[9];
    const float* Wk   = (const float*)d_in[10];
    const float* bk   = (const float*)d_in[11];
    float* out = (float*)d_out;

    float* dQ = nullptr;
    float* dK = nullptr;
    cudaGetSymbolAddress((void**)&dQ, g_Q);
    cudaGetSymbolAddress((void**)&dK, g_K);

    // setup (x_proj + biases)
    k_setup<<<1, 1024>>>(w_ih, b_ih, b_hh, dec);

    // keys = node_emb @ Wk^T + bk   (M = 8*2048 flat, N = 256)
    k_gemm_nt<<<dim3(2, 128, 1), 256>>>(node, Wk, bk, dK, 0, 0, 0, 256);

    // LSTM scan -> g_Q
    k_lstm<<<64, 256>>>(w_hh, Wq, bq, z_g, h0);

    // S = Q @ K^T written straight into d_out (per batch)
    k_gemm_nt<<<dim3(16, 16, 8), 256>>>(dQ, dK, nullptr, out,
                                        (size_t)NN * MM, (size_t)NN * MM,
                                        (size_t)NN * NN, NN);

    // in-place masked softmax / argmax chain
    k_chain<<<8, 1024>>>(out);
}

// round 11
// speedup vs baseline: 1.2349x; 1.1810x over previous
#include <cuda_runtime.h>
#include <cstdint>
#include <cstddef>

#define NB 8
#define NN 2048
#define MM 256
#define GG 1024  // 4*MM

// ---------------- device-global scratch (no allocations allowed) -----------
__device__ float g_Q[NB * NN * MM];   // q_t per (batch, step)   16 MB
__device__ float g_K[NB * NN * MM];   // keys                    16 MB
__device__ float g_xb[GG];            // x_proj + b_ih + b_hh
__device__ int   g_rank[NB * NN];     // step at which index was selected

// ---------------- helpers --------------------------------------------------
__device__ __forceinline__ uint32_t smem_u32(const void* p) {
    return (uint32_t)__cvta_generic_to_shared(p);
}
__device__ __forceinline__ uint32_t mapa_rank(uint32_t laddr, uint32_t rank) {
    uint32_t r;
    asm("mapa.shared::cluster.u32 %0, %1, %2;" : "=r"(r) : "r"(laddr), "r"(rank));
    return r;
}
__device__ __forceinline__ void st_cluster_f32(uint32_t addr, float v) {
    asm volatile("st.shared::cluster.f32 [%0], %1;" :: "r"(addr), "f"(v) : "memory");
}
__device__ __forceinline__ void cluster_sync_() {
    asm volatile("barrier.cluster.arrive.aligned;" ::: "memory");
    asm volatile("barrier.cluster.wait.aligned;" ::: "memory");
}
__device__ __forceinline__ uint32_t fkey(float f) {
    uint32_t u = __float_as_uint(f);
    return (u & 0x80000000u) ? ~u : (u | 0x80000000u);  // monotonic float->uint
}
__device__ __forceinline__ float sigm(float x) { return 1.0f / (1.0f + expf(-x)); }

// packed f32x2 ops (sm_103a; ptxas never auto-fuses these)
__device__ __forceinline__ uint64_t fma2(uint64_t a, uint64_t b, uint64_t c) {
    uint64_t d;
    asm("fma.rn.f32x2 %0, %1, %2, %3;" : "=l"(d) : "l"(a), "l"(b), "l"(c));
    return d;
}
__device__ __forceinline__ uint64_t add2(uint64_t a, uint64_t b) {
    uint64_t d;
    asm("add.rn.f32x2 %0, %1, %2;" : "=l"(d) : "l"(a), "l"(b));
    return d;
}
__device__ __forceinline__ uint64_t pack2(float lo, float hi) {
    uint64_t d;
    asm("mov.b64 %0, {%1, %2};" : "=l"(d) : "r"(__float_as_uint(lo)), "r"(__float_as_uint(hi)));
    return d;
}
__device__ __forceinline__ float unpack_sum(uint64_t a) {
    uint32_t lo, hi;
    asm("mov.b64 {%0, %1}, %2;" : "=r"(lo), "=r"(hi) : "l"(a));
    return __uint_as_float(lo) + __uint_as_float(hi);
}
__device__ __forceinline__ void unpack2(uint64_t a, float& lo, float& hi) {
    uint32_t l, h;
    asm("mov.b64 {%0, %1}, %2;" : "=r"(l), "=r"(h) : "l"(a));
    lo = __uint_as_float(l); hi = __uint_as_float(h);
}

// ---------------- setup: g_xb = w_ih @ dec + b_ih + b_hh -------------------
__global__ void __launch_bounds__(1024) k_setup(
    const float* __restrict__ w_ih, const float* __restrict__ b_ih,
    const float* __restrict__ b_hh, const float* __restrict__ dec) {
    __shared__ __align__(16) float ds[MM];
    int g = threadIdx.x;
    if (g < MM) ds[g] = dec[g];
    __syncthreads();
    const float4* w4 = (const float4*)(w_ih + (size_t)g * MM);
    const float4* d4 = (const float4*)ds;
    float acc = 0.f;
#pragma unroll 16
    for (int i = 0; i < MM / 4; i++) {
        float4 w = w4[i], d = d4[i];
        acc += w.x * d.x + w.y * d.y + w.z * d.z + w.w * d.w;
    }
    g_xb[g] = acc + b_ih[g] + b_hh[g];
}

// ---------------- phase 1: LSTM scan, 8-CTA cluster per batch --------------
__global__ void __cluster_dims__(8, 1, 1) __launch_bounds__(256, 1)
k_lstm(const float* __restrict__ w_hh, const float* __restrict__ Wq,
       const float* __restrict__ bq, const float* __restrict__ z_g,
       const float* __restrict__ h0) {
    int tid = threadIdx.x;
    uint32_t rk;
    asm("mov.u32 %0, %%cluster_ctarank;" : "=r"(rk));
    int b = blockIdx.x >> 3;

    __shared__ __align__(16) float h_sm[2][MM];   // cluster-written, dbl-buffered
    __shared__ __align__(16) float gloc[128];     // local gates [g4*32 + j]

    // gate shard
    int rloc = tid >> 1;
    int kh = tid & 1;
    int g4 = rloc >> 5, j = rloc & 31;
    int grow = g4 * 256 + (int)rk * 32 + j;
    uint64_t wg[64];
    {
        const uint64_t* wp = (const uint64_t*)(w_hh + (size_t)grow * MM + kh * 128);
#pragma unroll
        for (int i = 0; i < 64; i++) wg[i] = wp[i];
    }
    float xb = g_xb[grow];

    // q shard
    int qrow = (int)rk * 32 + (tid >> 3);
    int ks = tid & 7;
    uint64_t wq2[16];
    {
        const uint64_t* qp = (const uint64_t*)(Wq + (size_t)qrow * MM + ks * 32);
#pragma unroll
        for (int i = 0; i < 16; i++) wq2[i] = qp[i];
    }
    float bqv = bq[qrow];

    uint32_t ha[8];
    {
        uint32_t la = smem_u32(&h_sm[0][0]);
#pragma unroll
        for (int r = 0; r < 8; r++) ha[r] = mapa_rank(la, (uint32_t)r);
    }

    h_sm[0][tid] = h0[tid];
    float c_reg = 0.f;
    if (tid < 32) c_reg = z_g[b * MM + (int)rk * 32 + tid];
    __syncthreads();
    cluster_sync_();

    float* Qb = g_Q + (size_t)b * NN * MM;

    for (int t = 0; t < NN; t++) {
        {
            const uint64_t* h2 = (const uint64_t*)(h_sm[t & 1] + kh * 128);
            uint64_t a0 = 0, a1 = 0, a2 = 0, a3 = 0;
#pragma unroll
            for (int i = 0; i < 64; i += 4) {
                a0 = fma2(wg[i + 0], h2[i + 0], a0);
                a1 = fma2(wg[i + 1], h2[i + 1], a1);
                a2 = fma2(wg[i + 2], h2[i + 2], a2);
                a3 = fma2(wg[i + 3], h2[i + 3], a3);
            }
            float s = unpack_sum(add2(add2(a0, a1), add2(a2, a3)));
            s += __shfl_xor_sync(0xffffffffu, s, 1);
            if (kh == 0) gloc[rloc] = s + xb;
        }
        __syncthreads();

        if (tid < 32) {
            float gi = gloc[tid], gf = gloc[32 + tid];
            float gg = gloc[64 + tid], go = gloc[96 + tid];
            float c = sigm(gf) * c_reg + sigm(gi) * tanhf(gg);
            c_reg = c;
            float hv = sigm(go) * tanhf(c);
            uint32_t off = (uint32_t)((((t + 1) & 1) * MM + (int)rk * 32 + tid) * 4);
#pragma unroll
            for (int r = 0; r < 8; r++) st_cluster_f32(ha[r] + off, hv);
        }
        cluster_sync_();  // h(t) visible everywhere

        {
            const uint64_t* hq = (const uint64_t*)(h_sm[(t + 1) & 1] + ks * 32);
            uint64_t b0 = 0, b1 = 0;
#pragma unroll
            for (int i = 0; i < 16; i += 2) {
                b0 = fma2(wq2[i], hq[i], b0);
                b1 = fma2(wq2[i + 1], hq[i + 1], b1);
            }
            float q = unpack_sum(add2(b0, b1));
            q += __shfl_xor_sync(0xffffffffu, q, 4);
            q += __shfl_xor_sync(0xffffffffu, q, 2);
            q += __shfl_xor_sync(0xffffffffu, q, 1);
            if (ks == 0) Qb[(size_t)t * MM + qrow] = q + bqv;
        }
    }
}

// ---------------- phase 2: C = A @ B^T (+bias), K=256, packed f32x2 --------
__global__ void __launch_bounds__(256) k_gemm_nt(
    const float* __restrict__ A, const float* __restrict__ B,
    const float* __restrict__ bias, float* __restrict__ C,
    size_t sA, size_t sB, size_t sC, int ldc) {
    A += (size_t)blockIdx.z * sA;
    B += (size_t)blockIdx.z * sB;
    C += (size_t)blockIdx.z * sC;
    int row0 = blockIdx.y * 128, col0 = blockIdx.x * 128;

    __shared__ __align__(16) float As[16][132];
    __shared__ __align__(16) float Bs[16][132];

    int tid = threadIdx.x;
    int tx = tid & 15, ty = tid >> 4;
    uint64_t acc2[8][4] = {};

    for (int kt = 0; kt < 256; kt += 16) {
#pragma unroll
        for (int l = 0; l < 2; l++) {
            int f = tid + 256 * l;
            int i = f >> 2, c4 = (f & 3) * 4;
            float4 a = *(const float4*)(A + (size_t)(row0 + i) * 256 + kt + c4);
            As[c4 + 0][i] = a.x; As[c4 + 1][i] = a.y; As[c4 + 2][i] = a.z; As[c4 + 3][i] = a.w;
            float4 bv = *(const float4*)(B + (size_t)(col0 + i) * 256 + kt + c4);
            Bs[c4 + 0][i] = bv.x; Bs[c4 + 1][i] = bv.y; Bs[c4 + 2][i] = bv.z; Bs[c4 + 3][i] = bv.w;
        }
        __syncthreads();
#pragma unroll
        for (int kk = 0; kk < 16; kk++) {
            float4 t0 = *(const float4*)(&As[kk][ty * 8]);
            float4 t1 = *(const float4*)(&As[kk][ty * 8 + 4]);
            uint64_t ad[8];
            ad[0] = pack2(t0.x, t0.x); ad[1] = pack2(t0.y, t0.y);
            ad[2] = pack2(t0.z, t0.z); ad[3] = pack2(t0.w, t0.w);
            ad[4] = pack2(t1.x, t1.x); ad[5] = pack2(t1.y, t1.y);
            ad[6] = pack2(t1.z, t1.z); ad[7] = pack2(t1.w, t1.w);
            const uint64_t* bsp = (const uint64_t*)(&Bs[kk][tx * 8]);
            uint64_t bp0 = bsp[0], bp1 = bsp[1], bp2 = bsp[2], bp3 = bsp[3];
#pragma unroll
            for (int i = 0; i < 8; i++) {
                acc2[i][0] = fma2(ad[i], bp0, acc2[i][0]);
                acc2[i][1] = fma2(ad[i], bp1, acc2[i][1]);
                acc2[i][2] = fma2(ad[i], bp2, acc2[i][2]);
                acc2[i][3] = fma2(ad[i], bp3, acc2[i][3]);
            }
        }
        __syncthreads();
    }

    float bs[8];
#pragma unroll
    for (int jj = 0; jj < 8; jj++) bs[jj] = bias ? bias[col0 + tx * 8 + jj] : 0.f;

#pragma unroll
    for (int i = 0; i < 8; i++) {
        float v[8];
#pragma unroll
        for (int jp = 0; jp < 4; jp++) unpack2(acc2[i][jp], v[2 * jp], v[2 * jp + 1]);
        float* cp = C + (size_t)(row0 + ty * 8 + i) * ldc + col0 + tx * 8;
        float4 v0 = make_float4(v[0] + bs[0], v[1] + bs[1], v[2] + bs[2], v[3] + bs[3]);
        float4 v1 = make_float4(v[4] + bs[4], v[5] + bs[5], v[6] + bs[6], v[7] + bs[7]);
        *(float4*)cp = v0;
        *(float4*)(cp + 4) = v1;
    }
}

// ---------------- phase 3a: serial masked-argmax chain (selection only) ----
// One CTA (1024 threads) per batch. Per step: REDUX max of fkey + REDUX min
// index among matchers (first-occurrence tie-break), cross-warp via smem,
// one __syncthreads per step. No exp, no sum, no row writes in the loop.
__global__ void __launch_bounds__(1024, 1) k_select(const float* __restrict__ S) {
    int b = blockIdx.x;
    int tid = threadIdx.x;
    int lane = tid & 31, warp = tid >> 5;
    const float* base = S + (size_t)b * NN * NN;
    int n0 = tid * 2;
    bool u0 = false, u1 = false;
    int* rkb = g_rank + b * NN;

    __shared__ uint32_t kmax_s[2][32];
    __shared__ uint32_t kidx_s[2][32];

    float2 cur = *(const float2*)(base + n0);
    for (int t = 0; t < NN; t++) {
        float2 nxt = cur;
        if (t + 1 < NN) nxt = *(const float2*)(base + (size_t)(t + 1) * NN + n0);

        uint32_t k0 = u0 ? 0u : fkey(cur.x);
        uint32_t k1 = u1 ? 0u : fkey(cur.y);
        uint32_t km = k0 > k1 ? k0 : k1;
        uint32_t wmax = __reduce_max_sync(0xffffffffu, km);
        uint32_t ci = 0xffffffffu;
        if (k0 == wmax) ci = (uint32_t)n0;
        else if (k1 == wmax) ci = (uint32_t)(n0 + 1);
        uint32_t widx = __reduce_min_sync(0xffffffffu, ci);
        if (lane == 0) { kmax_s[t & 1][warp] = wmax; kidx_s[t & 1][warp] = widx; }
        __syncthreads();
        uint32_t vm = kmax_s[t & 1][lane];
        uint32_t vi = kidx_s[t & 1][lane];
        uint32_t gmax = __reduce_max_sync(0xffffffffu, vm);
        uint32_t ci2 = (vm == gmax) ? vi : 0xffffffffu;
        uint32_t gidx = __reduce_min_sync(0xffffffffu, ci2);

        if (gidx == (uint32_t)n0)            { u0 = true; rkb[n0] = t; }
        else if (gidx == (uint32_t)(n0 + 1)) { u1 = true; rkb[n0 + 1] = t; }
        cur = nxt;
    }
}

// ---------------- phase 3b: fully parallel masked softmax ------------------
// One CTA per (batch, step) row, in-place in d_out.
// probs[t,i] = exp(s[t,i]) * [rank[i] >= t] / sum   (masked exp == exact 0,
// matching the reference's underflowed exp(s - 1e9)).
__global__ void __launch_bounds__(256) k_probs(float* __restrict__ out) {
    int t = blockIdx.x, b = blockIdx.y;
    float* row = out + ((size_t)b * NN + t) * NN;
    const int* rkb = g_rank + b * NN;
    int tid = threadIdx.x;
    int lane = tid & 31, warp = tid >> 5;

    __shared__ float ps[8];
    float e[8];
    float s = 0.f;
#pragma unroll
    for (int jj = 0; jj < 2; jj++) {
        int i = tid * 4 + jj * 1024;
        float4 v = *(const float4*)(row + i);
        int4 r = *(const int4*)(rkb + i);
        float e0 = (r.x >= t) ? expf(v.x) : 0.f;
        float e1 = (r.y >= t) ? expf(v.y) : 0.f;
        float e2 = (r.z >= t) ? expf(v.z) : 0.f;
        float e3 = (r.w >= t) ? expf(v.w) : 0.f;
        e[jj * 4 + 0] = e0; e[jj * 4 + 1] = e1;
        e[jj * 4 + 2] = e2; e[jj * 4 + 3] = e3;
        s += (e0 + e1) + (e2 + e3);
    }
#pragma unroll
    for (int m = 16; m; m >>= 1) s += __shfl_xor_sync(0xffffffffu, s, m);
    if (lane == 0) ps[warp] = s;
    __syncthreads();
    float tot = ((ps[0] + ps[1]) + (ps[2] + ps[3]))
              + ((ps[4] + ps[5]) + (ps[6] + ps[7]));
    float inv = __fdividef(1.f, tot);
#pragma unroll
    for (int jj = 0; jj < 2; jj++) {
        int i = tid * 4 + jj * 1024;
        *(float4*)(row + i) = make_float4(e[jj * 4 + 0] * inv, e[jj * 4 + 1] * inv,
                                          e[jj * 4 + 2] * inv, e[jj * 4 + 3] * inv);
    }
}

// ---------------- launch ---------------------------------------------------
extern "C" void kernel_launch(void* const* d_in, const int* in_sizes, int n_in,
                              void* d_out, int out_size) {
    const float* node = (const float*)d_in[0];
    const float* z_g  = (const float*)d_in[1];
    const float* dec  = (const float*)d_in[2];
    const float* h0   = (const float*)d_in[3];
    const float* w_ih = (const float*)d_in[4];
    const float* w_hh = (const float*)d_in[5];
    const float* b_ih = (const float*)d_in[6];
    const float* b_hh = (const float*)d_in[7];
    const float* Wq   = (const float*)d_in[8];
    const float* bq   = (const float*)d_in[9];
    const float* Wk   = (const float*)d_in[10];
    const float* bk   = (const float*)d_in[11];
    float* out = (float*)d_out;

    float* dQ = nullptr;
    float* dK = nullptr;
    cudaGetSymbolAddress((void**)&dQ, g_Q);
    cudaGetSymbolAddress((void**)&dK, g_K);

    // setup (x_proj + biases)
    k_setup<<<1, 1024>>>(w_ih, b_ih, b_hh, dec);

    // keys = node_emb @ Wk^T + bk   (M = 8*2048 flat, N = 256)
    k_gemm_nt<<<dim3(2, 128, 1), 256>>>(node, Wk, bk, dK, 0, 0, 0, 256);

    // LSTM scan -> g_Q
    k_lstm<<<64, 256>>>(w_hh, Wq, bq, z_g, h0);

    // S = Q @ K^T written straight into d_out (per batch)
    k_gemm_nt<<<dim3(16, 16, 8), 256>>>(dQ, dK, nullptr, out,
                                        (size_t)NN * MM, (size_t)NN * MM,
                                        (size_t)NN * NN, NN);

    // serial selection chain (argmax order only) -> g_rank
    k_select<<<8, 1024>>>(out);

    // fully parallel masked softmax, in place
    k_probs<<<dim3(NN, NB), 256>>>(out);
}